// round 6
// baseline (speedup 1.0000x reference)
#include <cuda_runtime.h>

#define NQ 12
#define NS 4096
#define TPB 128
#define NL 3
#define NA 32          // amplitudes per thread (5 local bits)

__device__ float g_gates[NL * NQ * 8];

__global__ void prep_gates(const float* __restrict__ params) {
    int t = blockIdx.x * blockDim.x + threadIdx.x;
    if (t >= NL * NQ) return;
    float t0 = params[t * 3 + 0], t1 = params[t * 3 + 1], t2 = params[t * 3 + 2];
    float c0 = cosf(0.5f * t0), s0 = sinf(0.5f * t0);
    float cp = cosf(0.5f * t1), sp = sinf(0.5f * t1);
    float c2 = cosf(0.5f * t2), s2 = sinf(0.5f * t2);
    float A_re = cp * c0, A_im = -sp * c0;
    float B_re = -cp * s0, B_im = sp * s0;
    float C_re = cp * s0, C_im = sp * s0;
    float D_re = cp * c0, D_im = sp * c0;
    float* g = &g_gates[t * 8];
    g[0] = c2 * A_re - s2 * C_re;  g[1] = c2 * A_im - s2 * C_im;
    g[2] = c2 * B_re - s2 * D_re;  g[3] = c2 * B_im - s2 * D_im;
    g[4] = s2 * A_re + c2 * C_re;  g[5] = s2 * A_im + c2 * C_im;
    g[6] = s2 * B_re + c2 * D_re;  g[7] = s2 * B_im + c2 * D_im;
}

struct G2 { float2 g00, g01, g10, g11; };

__device__ __forceinline__ void apply_pair(const G2& g, float2& a, float2& b) {
    float2 na, nb;
    na.x = g.g00.x * a.x - g.g00.y * a.y + g.g01.x * b.x - g.g01.y * b.y;
    na.y = g.g00.x * a.y + g.g00.y * a.x + g.g01.x * b.y + g.g01.y * b.x;
    nb.x = g.g10.x * a.x - g.g10.y * a.y + g.g11.x * b.x - g.g11.y * b.y;
    nb.y = g.g10.x * a.y + g.g10.y * a.x + g.g11.x * b.y + g.g11.y * b.x;
    a = na; b = nb;
}

__device__ __forceinline__ G2 load_gate(const float* gsm, int l, int w) {
    const float* g = &gsm[(l * NQ + w) * 8];
    G2 r;
    r.g00 = make_float2(g[0], g[1]);
    r.g01 = make_float2(g[2], g[3]);
    r.g10 = make_float2(g[4], g[5]);
    r.g11 = make_float2(g[6], g[7]);
    return r;
}

__device__ __forceinline__ void gate_on_bit(const G2& g, float2 r[NA], int k) {
    #pragma unroll
    for (int l = 0; l < NA; l++)
        if (!(l & (1 << k))) apply_pair(g, r[l], r[l | (1 << k)]);
}

__device__ __forceinline__ void cnot_loc(float2 r[NA], int c, int tg) {
    #pragma unroll
    for (int l = 0; l < NA; l++)
        if ((l & (1 << c)) && !(l & (1 << tg))) {
            float2 tmp = r[l]; r[l] = r[l | (1 << tg)]; r[l | (1 << tg)] = tmp;
        }
}

// Stage maps. t = thread (7 bits), l = local (5 bits), g = 12-bit amp index.
// S0: l = g[11:7] (wires 0-4),  t = g[6:0]  (wires 5-11)
// S1: l = g[7:3]  (wires 4-8),  t = g[11:8]<<3 | g[2:0]
// S2: l = g[4:0]  (wires 7-11), t = g[11:5] (wires 0-6)
__device__ __forceinline__ int gS0(int t, int l) { return (l << 7) | t; }
__device__ __forceinline__ int gS1(int t, int l) { return ((t >> 3) << 8) | (l << 3) | (t & 7); }
__device__ __forceinline__ int gS2(int t, int l) { return (t << 5) | l; }
__device__ __forceinline__ int swz(int g, int sh, int mk) { return g ^ ((g >> sh) & mk); }

__global__ __launch_bounds__(TPB, 5) void qsim(
    const float* __restrict__ x, const float* __restrict__ head_w,
    const float* __restrict__ head_b, float* __restrict__ out) {
    __shared__ float2 st[NS];          // 32 KB transpose buffer
    __shared__ float gsm[NL * NQ * 8];
    __shared__ float csC[NQ], csS[NQ];
    __shared__ float wred[TPB / 32];

    int b = blockIdx.x, t = threadIdx.x;

    for (int i = t; i < NL * NQ * 8; i += TPB) gsm[i] = g_gates[i];
    if (t < NQ) {
        float xv = x[b * NQ + t];
        csC[t] = cosf(0.5f * xv);
        csS[t] = sinf(0.5f * xv);
    }
    __syncthreads();

    float2 r[NA];

    // --- Init: product state in S0 layout (t = wires 5..11, l = wires 0..4) ---
    {
        float rB = 1.f;
        #pragma unroll
        for (int w = 5; w < NQ; w++) {
            int bit = (t >> (11 - w)) & 1;
            rB *= bit ? csS[w] : csC[w];
        }
        int kB = __popc(t);
        #pragma unroll
        for (int l = 0; l < NA; l++) {
            float rA = 1.f;
            #pragma unroll
            for (int w = 0; w < 5; w++) {
                int bit = (l >> (4 - w)) & 1;
                rA *= bit ? csS[w] : csC[w];
            }
            float v = rA * rB;
            int m = (kB + __popc(l)) & 3;   // (-i)^m
            float2 a;
            a.x = (m == 0) ? v : ((m == 2) ? -v : 0.f);
            a.y = (m == 1) ? -v : ((m == 3) ? v : 0.f);
            r[l] = a;
        }
    }

    #define XPOSE(GSRC, GDST, SH, MK) do {                                 \
        __syncthreads();                                                   \
        _Pragma("unroll")                                                  \
        for (int i_ = 0; i_ < NA; i_++) st[swz(GSRC(t, i_), SH, MK)] = r[i_]; \
        __syncthreads();                                                   \
        _Pragma("unroll")                                                  \
        for (int i_ = 0; i_ < NA; i_++) r[i_] = st[swz(GDST(t, i_), SH, MK)]; \
    } while (0)

    for (int l = 0; l < NL; l++) {
        // S0: wires 0-4 on local bits 4..0; gates G0..G4; CNOTs (0,1)..(3,4)
        {
            G2 G0 = load_gate(gsm, l, 0);  gate_on_bit(G0, r, 4);
            G2 G1 = load_gate(gsm, l, 1);  gate_on_bit(G1, r, 3);
            G2 Gg2 = load_gate(gsm, l, 2); gate_on_bit(Gg2, r, 2);
            G2 G3 = load_gate(gsm, l, 3);  gate_on_bit(G3, r, 1);
            G2 G4 = load_gate(gsm, l, 4);  gate_on_bit(G4, r, 0);
            cnot_loc(r, 4, 3); cnot_loc(r, 3, 2); cnot_loc(r, 2, 1); cnot_loc(r, 1, 0);
        }
        XPOSE(gS0, gS1, 6, 0xC);
        // S1: wires 4(l4),5(l3),6(l2),7(l1),8(l0); gates G5..G8; CNOTs (4,5)..(7,8)
        {
            G2 G5 = load_gate(gsm, l, 5); gate_on_bit(G5, r, 3);
            G2 G6 = load_gate(gsm, l, 6); gate_on_bit(G6, r, 2);
            G2 G7 = load_gate(gsm, l, 7); gate_on_bit(G7, r, 1);
            G2 G8 = load_gate(gsm, l, 8); gate_on_bit(G8, r, 0);
            cnot_loc(r, 4, 3); cnot_loc(r, 3, 2); cnot_loc(r, 2, 1); cnot_loc(r, 1, 0);
        }
        XPOSE(gS1, gS2, 5, 0xF);
        // S2: wires 7(l4),8(l3),9(l2),10(l1),11(l0); gates G9..G11; CNOTs (8,9)..(10,11)
        {
            G2 G9 = load_gate(gsm, l, 9);  gate_on_bit(G9, r, 2);
            G2 Ga = load_gate(gsm, l, 10); gate_on_bit(Ga, r, 1);
            G2 Gb = load_gate(gsm, l, 11); gate_on_bit(Gb, r, 0);
            cnot_loc(r, 3, 2); cnot_loc(r, 2, 1); cnot_loc(r, 1, 0);
        }
        if (l < NL - 1) XPOSE(gS2, gS0, 5, 0xF);
    }

    // --- Readout from S2 registers: t = wires 0..6, l = wires 7..11 ---
    float swt = 0.f;
    #pragma unroll
    for (int w = 0; w < 7; w++)
        swt += ((t >> (6 - w)) & 1) ? -head_w[w] : head_w[w];
    float acc = 0.f;
    #pragma unroll
    for (int l = 0; l < NA; l++) {
        float2 a = r[l];
        float p = a.x * a.x + a.y * a.y;
        float swl = 0.f;
        #pragma unroll
        for (int w = 7; w < 12; w++)
            swl += ((l >> (11 - w)) & 1) ? -head_w[w] : head_w[w];
        acc = fmaf(p, swt + swl, acc);
    }
    #pragma unroll
    for (int o = 16; o > 0; o >>= 1) acc += __shfl_xor_sync(0xFFFFFFFFu, acc, o);
    if ((t & 31) == 0) wred[t >> 5] = acc;
    __syncthreads();
    if (t == 0) {
        float tot = 0.f;
        #pragma unroll
        for (int i = 0; i < TPB / 32; i++) tot += wred[i];
        out[b] = tot + head_b[0];
    }
}

extern "C" void kernel_launch(void* const* d_in, const int* in_sizes, int n_in,
                              void* d_out, int out_size) {
    const float* x      = (const float*)d_in[0];
    const float* params = (const float*)d_in[1];
    const float* head_w = (const float*)d_in[2];
    const float* head_b = (const float*)d_in[3];
    float* out = (float*)d_out;
    int B = in_sizes[0] / NQ;
    prep_gates<<<1, 64>>>(params);
    qsim<<<B, TPB>>>(x, head_w, head_b, out);
}

// round 7
// speedup vs baseline: 2.3970x; 2.3970x over previous
#include <cuda_runtime.h>

#define NQ 12
#define NS 4096
#define TPB 256
#define NL 3

__device__ float g_gates[NL * NQ * 8];

__global__ void prep_gates(const float* __restrict__ params) {
    int t = blockIdx.x * blockDim.x + threadIdx.x;
    if (t >= NL * NQ) return;
    float t0 = params[t * 3 + 0], t1 = params[t * 3 + 1], t2 = params[t * 3 + 2];
    float c0 = cosf(0.5f * t0), s0 = sinf(0.5f * t0);
    float cp = cosf(0.5f * t1), sp = sinf(0.5f * t1);
    float c2 = cosf(0.5f * t2), s2 = sinf(0.5f * t2);
    float A_re = cp * c0, A_im = -sp * c0;
    float B_re = -cp * s0, B_im = sp * s0;
    float C_re = cp * s0, C_im = sp * s0;
    float D_re = cp * c0, D_im = sp * c0;
    float* g = &g_gates[t * 8];
    g[0] = c2 * A_re - s2 * C_re;  g[1] = c2 * A_im - s2 * C_im;
    g[2] = c2 * B_re - s2 * D_re;  g[3] = c2 * B_im - s2 * D_im;
    g[4] = s2 * A_re + c2 * C_re;  g[5] = s2 * A_im + c2 * C_im;
    g[6] = s2 * B_re + c2 * D_re;  g[7] = s2 * B_im + c2 * D_im;
}

struct G2 { float2 g00, g01, g10, g11; };

__device__ __forceinline__ float2 cmul(float2 a, float2 b) {
    return make_float2(a.x * b.x - a.y * b.y, a.x * b.y + a.y * b.x);
}

__device__ __forceinline__ void apply_pair(const G2& g, float2& a, float2& b) {
    float2 na, nb;
    na.x = g.g00.x * a.x - g.g00.y * a.y + g.g01.x * b.x - g.g01.y * b.y;
    na.y = g.g00.x * a.y + g.g00.y * a.x + g.g01.x * b.y + g.g01.y * b.x;
    nb.x = g.g10.x * a.x - g.g10.y * a.y + g.g11.x * b.x - g.g11.y * b.y;
    nb.y = g.g10.x * a.y + g.g10.y * a.x + g.g11.x * b.y + g.g11.y * b.x;
    a = na; b = nb;
}

__device__ __forceinline__ G2 load_gate(const float* gsm, int l, int w) {
    const float* g = &gsm[(l * NQ + w) * 8];
    G2 r;
    r.g00 = make_float2(g[0], g[1]);
    r.g01 = make_float2(g[2], g[3]);
    r.g10 = make_float2(g[4], g[5]);
    r.g11 = make_float2(g[6], g[7]);
    return r;
}

__device__ __forceinline__ void gate_on_bit(const G2& g, float2 r[16], int k) {
    #pragma unroll
    for (int l = 0; l < 16; l++)
        if (!(l & (1 << k))) apply_pair(g, r[l], r[l | (1 << k)]);
}

__device__ __forceinline__ void cnot_loc(float2 r[16], int c, int tg) {
    #pragma unroll
    for (int l = 0; l < 16; l++)
        if ((l & (1 << c)) && !(l & (1 << tg))) {
            float2 tmp = r[l]; r[l] = r[l | (1 << tg)]; r[l | (1 << tg)] = tmp;
        }
}

// Stage maps (verified R3/R5). t = thread (8 bits), l = local (4 bits).
__device__ __forceinline__ int gS0(int t, int l) { return (l << 8) | t; }
__device__ __forceinline__ int gS1(int t, int l) { return ((t >> 5) << 9) | (l << 5) | (t & 31); }
__device__ __forceinline__ int gS2(int t, int l) { return ((t >> 5) << 9) | (((t >> 2) & 7) << 6) | (l << 2) | (t & 3); }
__device__ __forceinline__ int gS3(int t, int l) { return ((t >> 5) << 9) | ((t & 31) << 4) | l; }
__device__ __forceinline__ int swz(int g, int m) { return g ^ ((g >> 4) & m); }

__global__ __launch_bounds__(TPB, 3) void qsim(
    const float* __restrict__ x, const float* __restrict__ head_w,
    const float* __restrict__ head_b, float* __restrict__ out) {
    extern __shared__ float2 stbuf[];          // 2 * 4096 float2 = 64 KB (double buffer)
    float2* st0 = stbuf;
    float2* st1 = stbuf + NS;
    __shared__ float gsm[NL * NQ * 8];
    __shared__ float2 vsm[NQ][2];              // per-wire vector after RX + layer-1 gate
    __shared__ float wred[TPB / 32];

    int b = blockIdx.x, t = threadIdx.x;

    for (int i = t; i < NL * NQ * 8; i += TPB) gsm[i] = g_gates[i];
    if (t < NQ) {
        // v_w = G_{layer0,w} @ [cos(x/2), -i sin(x/2)]  (layer-1 gate absorbed into init)
        float xv = x[b * NQ + t];
        float c = cosf(0.5f * xv), s = sinf(0.5f * xv);
        const float* g = &g_gates[t * 8];      // layer 0, wire t
        vsm[t][0] = make_float2(g[0] * c + s * g[3], g[1] * c - s * g[2]);
        vsm[t][1] = make_float2(g[4] * c + s * g[7], g[5] * c - s * g[6]);
    }
    __syncthreads();

    float2 r[16];

    // --- Init in S0 layout with layer-1 gates AND layer-1 CNOT chain absorbed ---
    // Target index g (post-CNOT-chain): source bits s_w = bit_w(g) ^ bit_{w-1}(g).
    // S0: t = g[7:0] (wires 4..11), l = g[11:8] (wires 0..3, l3=wire0..l0=wire3).
    {
        int u = t ^ (t >> 1);                  // adjacent-XOR of thread bits
        // P_t = prod_{w=5..11} v_w[s_w], s_w = (u >> (11-w)) & 1
        float2 P = vsm[5][(u >> 6) & 1];
        #pragma unroll
        for (int w = 6; w < NQ; w++) P = cmul(P, vsm[w][(u >> (11 - w)) & 1]);
        int t7 = (t >> 7) & 1;                 // bit of wire 4 in g
        // W34[(l1<<1)|l0] = P * v3[l1^l0] * v4[t7^l0]
        float2 W34[4];
        #pragma unroll
        for (int j = 0; j < 4; j++) {
            int l1 = j >> 1, l0 = j & 1;
            W34[j] = cmul(cmul(vsm[3][l1 ^ l0], vsm[4][t7 ^ l0]), P);
        }
        // W012[(l3<<2)|(l2<<1)|l1] = v0[l3] * v1[l3^l2] * v2[l2^l1]
        float2 W012[8];
        #pragma unroll
        for (int k = 0; k < 8; k++) {
            int l3 = k >> 2, l2 = (k >> 1) & 1, l1 = k & 1;
            W012[k] = cmul(cmul(vsm[0][l3], vsm[1][l3 ^ l2]), vsm[2][l2 ^ l1]);
        }
        #pragma unroll
        for (int l = 0; l < 16; l++)
            r[l] = cmul(W012[l >> 1], W34[l & 3]);
    }

    // Double-buffered transpose: ONE sync per transpose (write -> sync -> read).
    // Alternating buffers makes the write of transpose k+1 safe before others
    // finish reading transpose k's buffer.
    #define XPOSE(BUF, GSRC, GDST, MASK) do {                               \
        _Pragma("unroll")                                                   \
        for (int i_ = 0; i_ < 16; i_++) BUF[swz(GSRC(t, i_), MASK)] = r[i_]; \
        __syncthreads();                                                    \
        _Pragma("unroll")                                                   \
        for (int i_ = 0; i_ < 16; i_++) r[i_] = BUF[swz(GDST(t, i_), MASK)]; \
    } while (0)

    // Layers 2..3 (layer 1 fully absorbed above)
    for (int l = 1; l < NL; l++) {
        // S0: wires 0-3 on local bits 3..0
        {
            G2 G0 = load_gate(gsm, l, 0);  gate_on_bit(G0, r, 3);
            G2 G1 = load_gate(gsm, l, 1);  gate_on_bit(G1, r, 2);
            G2 Gc = load_gate(gsm, l, 2);  gate_on_bit(Gc, r, 1);
            G2 G3 = load_gate(gsm, l, 3);  gate_on_bit(G3, r, 0);
            cnot_loc(r, 3, 2); cnot_loc(r, 2, 1); cnot_loc(r, 1, 0);
        }
        XPOSE(st0, gS0, gS1, 0);
        // S1: wires 3(l3),4(l2),5(l1),6(l0); gates on 4,5,6
        {
            G2 G4 = load_gate(gsm, l, 4); gate_on_bit(G4, r, 2);
            G2 G5 = load_gate(gsm, l, 5); gate_on_bit(G5, r, 1);
            G2 G6 = load_gate(gsm, l, 6); gate_on_bit(G6, r, 0);
            cnot_loc(r, 3, 2); cnot_loc(r, 2, 1); cnot_loc(r, 1, 0);
        }
        XPOSE(st1, gS1, gS2, 0xC);
        // S2: wires 6(l3),7(l2),8(l1),9(l0); gates on 7,8,9
        {
            G2 G7 = load_gate(gsm, l, 7); gate_on_bit(G7, r, 2);
            G2 G8 = load_gate(gsm, l, 8); gate_on_bit(G8, r, 1);
            G2 G9 = load_gate(gsm, l, 9); gate_on_bit(G9, r, 0);
            cnot_loc(r, 3, 2); cnot_loc(r, 2, 1); cnot_loc(r, 1, 0);
        }
        XPOSE(st0, gS2, gS3, 0xF);
        // S3: wires 8(l3),9(l2),10(l1),11(l0); gates on 10,11
        {
            G2 Ga = load_gate(gsm, l, 10); gate_on_bit(Ga, r, 1);
            G2 Gb = load_gate(gsm, l, 11); gate_on_bit(Gb, r, 0);
            cnot_loc(r, 2, 1); cnot_loc(r, 1, 0);
        }
        if (l < NL - 1) XPOSE(st1, gS3, gS0, 0xF);
    }

    // --- Readout from S3 registers: g[11:4] = t bits (wires 0..7), g[3:0] = l (wires 8..11) ---
    float swt = 0.f;
    {
        int g = gS3(t, 0);
        #pragma unroll
        for (int w = 0; w < 8; w++)
            swt += ((g >> (11 - w)) & 1) ? -head_w[w] : head_w[w];
    }
    float acc = 0.f;
    #pragma unroll
    for (int l = 0; l < 16; l++) {
        float2 a = r[l];
        float p = a.x * a.x + a.y * a.y;
        float swl = 0.f;
        #pragma unroll
        for (int w = 8; w < 12; w++)
            swl += ((l >> (11 - w)) & 1) ? -head_w[w] : head_w[w];
        acc = fmaf(p, swt + swl, acc);
    }
    #pragma unroll
    for (int o = 16; o > 0; o >>= 1) acc += __shfl_xor_sync(0xFFFFFFFFu, acc, o);
    if ((t & 31) == 0) wred[t >> 5] = acc;
    __syncthreads();
    if (t == 0) {
        float tot = 0.f;
        #pragma unroll
        for (int i = 0; i < TPB / 32; i++) tot += wred[i];
        out[b] = tot + head_b[0];
    }
}

#define DYN_SMEM (2 * NS * sizeof(float2))

extern "C" void kernel_launch(void* const* d_in, const int* in_sizes, int n_in,
                              void* d_out, int out_size) {
    const float* x      = (const float*)d_in[0];
    const float* params = (const float*)d_in[1];
    const float* head_w = (const float*)d_in[2];
    const float* head_b = (const float*)d_in[3];
    float* out = (float*)d_out;
    int B = in_sizes[0] / NQ;
    static int smem_set = 0;
    if (!smem_set) {
        cudaFuncSetAttribute(qsim, cudaFuncAttributeMaxDynamicSharedMemorySize, DYN_SMEM);
        smem_set = 1;
    }
    prep_gates<<<1, 64>>>(params);
    qsim<<<B, TPB, DYN_SMEM>>>(x, head_w, head_b, out);
}

// round 8
// speedup vs baseline: 2.4342x; 1.0155x over previous
#include <cuda_runtime.h>

#define NQ 12
#define NS 4096
#define TPB 256
#define NL 3

__device__ float g_gates[NL * NQ * 8];

__global__ void prep_gates(const float* __restrict__ params) {
    int t = blockIdx.x * blockDim.x + threadIdx.x;
    if (t >= NL * NQ) return;
    float t0 = params[t * 3 + 0], t1 = params[t * 3 + 1], t2 = params[t * 3 + 2];
    float c0 = cosf(0.5f * t0), s0 = sinf(0.5f * t0);
    float cp = cosf(0.5f * t1), sp = sinf(0.5f * t1);
    float c2 = cosf(0.5f * t2), s2 = sinf(0.5f * t2);
    float A_re = cp * c0, A_im = -sp * c0;
    float B_re = -cp * s0, B_im = sp * s0;
    float C_re = cp * s0, C_im = sp * s0;
    float D_re = cp * c0, D_im = sp * c0;
    float* g = &g_gates[t * 8];
    g[0] = c2 * A_re - s2 * C_re;  g[1] = c2 * A_im - s2 * C_im;
    g[2] = c2 * B_re - s2 * D_re;  g[3] = c2 * B_im - s2 * D_im;
    g[4] = s2 * A_re + c2 * C_re;  g[5] = s2 * A_im + c2 * C_im;
    g[6] = s2 * B_re + c2 * D_re;  g[7] = s2 * B_im + c2 * D_im;
}

struct G2 { float2 g00, g01, g10, g11; };

__device__ __forceinline__ float2 cmul(float2 a, float2 b) {
    return make_float2(a.x * b.x - a.y * b.y, a.x * b.y + a.y * b.x);
}

__device__ __forceinline__ void apply_pair(const G2& g, float2& a, float2& b) {
    float2 na, nb;
    na.x = g.g00.x * a.x - g.g00.y * a.y + g.g01.x * b.x - g.g01.y * b.y;
    na.y = g.g00.x * a.y + g.g00.y * a.x + g.g01.x * b.y + g.g01.y * b.x;
    nb.x = g.g10.x * a.x - g.g10.y * a.y + g.g11.x * b.x - g.g11.y * b.y;
    nb.y = g.g10.x * a.y + g.g10.y * a.x + g.g11.x * b.y + g.g11.y * b.x;
    a = na; b = nb;
}

// Gates in smem as float4 pairs -> 2x LDS.128 per gate
__device__ __forceinline__ G2 load_gate(const float4* gsm4, int l, int w) {
    float4 p0 = gsm4[(l * NQ + w) * 2 + 0];
    float4 p1 = gsm4[(l * NQ + w) * 2 + 1];
    G2 r;
    r.g00 = make_float2(p0.x, p0.y);
    r.g01 = make_float2(p0.z, p0.w);
    r.g10 = make_float2(p1.x, p1.y);
    r.g11 = make_float2(p1.z, p1.w);
    return r;
}

__device__ __forceinline__ void gate_on_bit(const G2& g, float2 r[16], int k) {
    #pragma unroll
    for (int l = 0; l < 16; l++)
        if (!(l & (1 << k))) apply_pair(g, r[l], r[l | (1 << k)]);
}

__device__ __forceinline__ void cnot_loc(float2 r[16], int c, int tg) {
    #pragma unroll
    for (int l = 0; l < 16; l++)
        if ((l & (1 << c)) && !(l & (1 << tg))) {
            float2 tmp = r[l]; r[l] = r[l | (1 << tg)]; r[l | (1 << tg)] = tmp;
        }
}

// Stage maps (verified R3/R5/R7). t = thread (8 bits), l = local (4 bits).
// Warp id (t>>5) == g[11:9] in S1, S2, S3  ->  S1->S2 and S2->S3 are warp-local.
__device__ __forceinline__ int gS0(int t, int l) { return (l << 8) | t; }
__device__ __forceinline__ int gS1(int t, int l) { return ((t >> 5) << 9) | (l << 5) | (t & 31); }
__device__ __forceinline__ int gS2(int t, int l) { return ((t >> 5) << 9) | (((t >> 2) & 7) << 6) | (l << 2) | (t & 3); }
__device__ __forceinline__ int gS3(int t, int l) { return ((t >> 5) << 9) | ((t & 31) << 4) | l; }
__device__ __forceinline__ int swz(int g, int m) { return g ^ ((g >> 4) & m); }

__global__ __launch_bounds__(TPB, 3) void qsim(
    const float* __restrict__ x, const float* __restrict__ head_w,
    const float* __restrict__ head_b, float* __restrict__ out) {
    extern __shared__ float2 stbuf[];          // 2 * 4096 float2 = 64 KB (double buffer)
    float2* st0 = stbuf;
    float2* st1 = stbuf + NS;
    __shared__ float4 gsm4[NL * NQ * 2];
    __shared__ float2 vsm[NQ][2];              // per-wire vector after RX + layer-1 gate
    __shared__ float wred[TPB / 32];

    int b = blockIdx.x, t = threadIdx.x;

    {
        float* gsm = (float*)gsm4;
        for (int i = t; i < NL * NQ * 8; i += TPB) gsm[i] = g_gates[i];
    }
    if (t < NQ) {
        // v_w = G_{layer0,w} @ [cos(x/2), -i sin(x/2)]  (layer-1 gate absorbed into init)
        float xv = x[b * NQ + t];
        float c = cosf(0.5f * xv), s = sinf(0.5f * xv);
        const float* g = &g_gates[t * 8];      // layer 0, wire t
        vsm[t][0] = make_float2(g[0] * c + s * g[3], g[1] * c - s * g[2]);
        vsm[t][1] = make_float2(g[4] * c + s * g[7], g[5] * c - s * g[6]);
    }
    __syncthreads();

    float2 r[16];

    // --- Init in S0 layout with layer-1 gates AND layer-1 CNOT chain absorbed ---
    // Post-chain index g: source bits s_w = bit_w(g) ^ bit_{w-1}(g).
    {
        int u = t ^ (t >> 1);
        float2 P = vsm[5][(u >> 6) & 1];
        #pragma unroll
        for (int w = 6; w < NQ; w++) P = cmul(P, vsm[w][(u >> (11 - w)) & 1]);
        int t7 = (t >> 7) & 1;
        float2 W34[4];
        #pragma unroll
        for (int j = 0; j < 4; j++) {
            int l1 = j >> 1, l0 = j & 1;
            W34[j] = cmul(cmul(vsm[3][l1 ^ l0], vsm[4][t7 ^ l0]), P);
        }
        float2 W012[8];
        #pragma unroll
        for (int k = 0; k < 8; k++) {
            int l3 = k >> 2, l2 = (k >> 1) & 1, l1 = k & 1;
            W012[k] = cmul(cmul(vsm[0][l3], vsm[1][l3 ^ l2]), vsm[2][l2 ^ l1]);
        }
        #pragma unroll
        for (int l = 0; l < 16; l++)
            r[l] = cmul(W012[l >> 1], W34[l & 3]);
    }

    // CTA-wide transpose (crosses warps): write -> bar -> read, double-buffered.
    #define XPOSE(BUF, GSRC, GDST, MASK) do {                               \
        _Pragma("unroll")                                                   \
        for (int i_ = 0; i_ < 16; i_++) BUF[swz(GSRC(t, i_), MASK)] = r[i_]; \
        __syncthreads();                                                    \
        _Pragma("unroll")                                                   \
        for (int i_ = 0; i_ < 16; i_++) r[i_] = BUF[swz(GDST(t, i_), MASK)]; \
    } while (0)

    // Warp-local transpose: both layouts keep warp id == g[11:9]; swizzle only
    // touches g[3:0]. Entire exchange stays in the warp's 512-amp block ->
    // __syncwarp() suffices (memory-ordering for the warp).
    #define XPOSE_W(BUF, GSRC, GDST, MASK) do {                             \
        _Pragma("unroll")                                                   \
        for (int i_ = 0; i_ < 16; i_++) BUF[swz(GSRC(t, i_), MASK)] = r[i_]; \
        __syncwarp();                                                       \
        _Pragma("unroll")                                                   \
        for (int i_ = 0; i_ < 16; i_++) r[i_] = BUF[swz(GDST(t, i_), MASK)]; \
    } while (0)

    // Layers 2..3 (layer 1 fully absorbed above)
    for (int l = 1; l < NL; l++) {
        // S0: wires 0-3 on local bits 3..0
        {
            G2 G0 = load_gate(gsm4, l, 0);  gate_on_bit(G0, r, 3);
            G2 G1 = load_gate(gsm4, l, 1);  gate_on_bit(G1, r, 2);
            G2 Gc = load_gate(gsm4, l, 2);  gate_on_bit(Gc, r, 1);
            G2 G3 = load_gate(gsm4, l, 3);  gate_on_bit(G3, r, 0);
            cnot_loc(r, 3, 2); cnot_loc(r, 2, 1); cnot_loc(r, 1, 0);
        }
        XPOSE(st0, gS0, gS1, 0);
        // S1: wires 3(l3),4(l2),5(l1),6(l0); gates on 4,5,6
        {
            G2 G4 = load_gate(gsm4, l, 4); gate_on_bit(G4, r, 2);
            G2 G5 = load_gate(gsm4, l, 5); gate_on_bit(G5, r, 1);
            G2 G6 = load_gate(gsm4, l, 6); gate_on_bit(G6, r, 0);
            cnot_loc(r, 3, 2); cnot_loc(r, 2, 1); cnot_loc(r, 1, 0);
        }
        XPOSE_W(st1, gS1, gS2, 0xC);
        // S2: wires 6(l3),7(l2),8(l1),9(l0); gates on 7,8,9
        {
            G2 G7 = load_gate(gsm4, l, 7); gate_on_bit(G7, r, 2);
            G2 G8 = load_gate(gsm4, l, 8); gate_on_bit(G8, r, 1);
            G2 G9 = load_gate(gsm4, l, 9); gate_on_bit(G9, r, 0);
            cnot_loc(r, 3, 2); cnot_loc(r, 2, 1); cnot_loc(r, 1, 0);
        }
        XPOSE_W(st0, gS2, gS3, 0xF);
        // S3: wires 8(l3),9(l2),10(l1),11(l0); gates on 10,11
        {
            G2 Ga = load_gate(gsm4, l, 10); gate_on_bit(Ga, r, 1);
            G2 Gb = load_gate(gsm4, l, 11); gate_on_bit(Gb, r, 0);
            cnot_loc(r, 2, 1); cnot_loc(r, 1, 0);
        }
        if (l < NL - 1) XPOSE(st1, gS3, gS0, 0xF);
    }

    // --- Readout from S3 registers: g[11:4] = t bits (wires 0..7), g[3:0] = l (wires 8..11) ---
    float swt = 0.f;
    {
        int g = gS3(t, 0);
        #pragma unroll
        for (int w = 0; w < 8; w++)
            swt += ((g >> (11 - w)) & 1) ? -head_w[w] : head_w[w];
    }
    float acc = 0.f;
    #pragma unroll
    for (int l = 0; l < 16; l++) {
        float2 a = r[l];
        float p = a.x * a.x + a.y * a.y;
        float swl = 0.f;
        #pragma unroll
        for (int w = 8; w < 12; w++)
            swl += ((l >> (11 - w)) & 1) ? -head_w[w] : head_w[w];
        acc = fmaf(p, swt + swl, acc);
    }
    #pragma unroll
    for (int o = 16; o > 0; o >>= 1) acc += __shfl_xor_sync(0xFFFFFFFFu, acc, o);
    if ((t & 31) == 0) wred[t >> 5] = acc;
    __syncthreads();
    if (t == 0) {
        float tot = 0.f;
        #pragma unroll
        for (int i = 0; i < TPB / 32; i++) tot += wred[i];
        out[b] = tot + head_b[0];
    }
}

#define DYN_SMEM (2 * NS * sizeof(float2))

extern "C" void kernel_launch(void* const* d_in, const int* in_sizes, int n_in,
                              void* d_out, int out_size) {
    const float* x      = (const float*)d_in[0];
    const float* params = (const float*)d_in[1];
    const float* head_w = (const float*)d_in[2];
    const float* head_b = (const float*)d_in[3];
    float* out = (float*)d_out;
    int B = in_sizes[0] / NQ;
    static int smem_set = 0;
    if (!smem_set) {
        cudaFuncSetAttribute(qsim, cudaFuncAttributeMaxDynamicSharedMemorySize, DYN_SMEM);
        smem_set = 1;
    }
    prep_gates<<<1, 64>>>(params);
    qsim<<<B, TPB, DYN_SMEM>>>(x, head_w, head_b, out);
}